// round 9
// baseline (speedup 1.0000x reference)
#include <cuda_runtime.h>

#define BB 8
#define CC 256
#define EE 128
#define NN 3136          // 56*56 = 49*64
#define NV 784           // NN/4
#define TPB 256
#define CHUNK 64
#define NCHK 49          // NN / CHUNK
#define P1B (BB * NCHK)  // 392
#define GRID P1B         // 392 blocks; <=4 CTAs/SM co-resident on 148 SMs

__device__ float g_ap[16 * CC];     // fold partials
__device__ float g_c0;
__device__ float g_tp[P1B * CC];    // partial t per (b,chunk)
__device__ float g_sbp[P1B];        // partial sbar
__device__ float g_d[BB * CC];
__device__ unsigned g_ctr;
__device__ volatile unsigned g_gen;

__device__ __forceinline__ void gbar() {
    __threadfence();
    __syncthreads();
    if (threadIdx.x == 0) {
        unsigned old = g_gen;
        if (atomicAdd(&g_ctr, 1u) == GRID - 1u) {
            g_ctr = 0u;
            __threadfence();
            g_gen = old + 1u;
        } else {
            while (g_gen == old) { __nanosleep(64); }
        }
    }
    __syncthreads();
}

__global__ void __launch_bounds__(TPB, 4)
fused_all(const float* __restrict__ x,
          const float* __restrict__ Wq, const float* __restrict__ bq,
          const float* __restrict__ Wk, const float* __restrict__ bk,
          const float* __restrict__ Wcat,
          const float* __restrict__ Wv, const float* __restrict__ bv,
          const float* __restrict__ Wexp, const float* __restrict__ bexp,
          float* __restrict__ out) {
    int tid = threadIdx.x;
    int bid = blockIdx.x;
    __shared__ float xs[CC * 33];  // x half-chunk, padded rows (conflict-free)
    __shared__ float sa[CC];       // a[] in P1; st[] in P2
    __shared__ float sp[CC];       // y-partials in P1; sm[] in P2
    __shared__ float ss[32];       // s for current 32-n half
    __shared__ float s_sbar;

    // ---------------- P0: fold partials + c0 ----------------
    if (bid < 16) {
        float acc = 0.f;
        int e0 = bid * 8;
        #pragma unroll
        for (int k = 0; k < 8; k++) {
            int e = e0 + k;
            acc = fmaf(Wcat[e], Wq[e * CC + tid],
                  fmaf(Wcat[EE + e], Wk[e * CC + tid], acc));
        }
        g_ap[bid * CC + tid] = acc;
    } else if (bid == 16 && tid < 32) {
        float c0 = 0.f;
        #pragma unroll
        for (int e = tid; e < EE; e += 32)
            c0 = fmaf(Wcat[e], bq[e], fmaf(Wcat[EE + e], bk[e], c0));
        #pragma unroll
        for (int o = 16; o > 0; o >>= 1) c0 += __shfl_down_sync(0xFFFFFFFFu, c0, o);
        if (tid == 0) g_c0 = c0;
    }
    gbar();

    // ---------------- P1: copy->smem, s, partial t, partial sbar ----------------
    {
        float a = 0.f;
        #pragma unroll
        for (int k = 0; k < 16; k++) a += g_ap[k * CC + tid];
        sa[tid] = a;

        int b = bid / NCHK;
        int nchunk = bid - b * NCHK;
        int n0 = nchunk * CHUNK;
        int w = tid >> 5, lane = tid & 31;
        const float* xb = x + (size_t)b * CC * NN;

        float tsum = 0.f;   // t accumulator for c = tid
        float sbp = 0.f;    // sbar partial (tid<32)
        __syncthreads();

        #pragma unroll
        for (int h = 0; h < 2; h++) {
            // copy: warp w loads c-rows w*32..w*32+31, lanes = 32 consecutive n
            const float* base = xb + (size_t)(w * 32) * NN + n0 + h * 32 + lane;
            #pragma unroll
            for (int j = 0; j < 32; j++)
                xs[(w * 32 + j) * 33 + lane] = base[(size_t)j * NN];
            __syncthreads();

            // y: thread (g = tid>>5, n = lane) sums its 32 c's from smem
            {
                float yacc = 0.f;
                #pragma unroll
                for (int j = 0; j < 32; j++)
                    yacc = fmaf(sa[w * 32 + j], xs[(w * 32 + j) * 33 + lane], yacc);
                sp[tid] = yacc;
            }
            __syncthreads();
            if (tid < 32) {
                float v = g_c0;
                #pragma unroll
                for (int g = 0; g < 8; g++) v += sp[g * 32 + tid];
                v = fmaxf(v, 0.f);
                ss[tid] = v;
                sbp += v;
            }
            __syncthreads();

            // t: thread tid owns c = tid; 32 LDS+FMA, no shuffles
            {
                const float* xr = &xs[tid * 33];
                float acc = 0.f;
                #pragma unroll
                for (int n = 0; n < 32; n++)
                    acc = fmaf(xr[n], ss[n], acc);
                tsum += acc;
            }
            __syncthreads();
        }
        g_tp[bid * CC + tid] = tsum;   // coalesced
        if (tid < 32) {
            #pragma unroll
            for (int o = 16; o > 0; o >>= 1) sbp += __shfl_xor_sync(0xFFFFFFFFu, sbp, o);
            if (tid == 0) g_sbp[bid] = sbp;
        }
    }
    gbar();

    // ---------------- P2: reduce t,sbar; m; d  (blocks 0..7) ----------------
    if (bid < BB) {
        int b = bid;
        float tv = 0.f;
        #pragma unroll
        for (int k = 0; k < NCHK; k++)
            tv += g_tp[(b * NCHK + k) * CC + tid];
        sa[tid] = tv * (1.0f / NN);       // sa = st
        if (tid < 32) {
            float sb = 0.f;
            for (int k = tid; k < NCHK; k += 32) sb += g_sbp[b * NCHK + k];
            #pragma unroll
            for (int o = 16; o > 0; o >>= 1) sb += __shfl_xor_sync(0xFFFFFFFFu, sb, o);
            if (tid == 0) s_sbar = sb * (1.0f / NN);
        }
        __syncthreads();
        float sbar = s_sbar;
        int w = tid >> 5, lane = tid & 31;

        // m[e] -> sp[e]
        #pragma unroll 4
        for (int j = 0; j < 16; j++) {
            int e = w * 16 + j;
            const float* wr = Wv + (size_t)e * CC;
            float acc = 0.f;
            #pragma unroll
            for (int k = 0; k < 8; k++)
                acc = fmaf(wr[lane + 32 * k], sa[lane + 32 * k], acc);
            #pragma unroll
            for (int o = 16; o > 0; o >>= 1)
                acc += __shfl_xor_sync(0xFFFFFFFFu, acc, o);
            if (lane == 0) sp[e] = acc + bv[e] * sbar;
        }
        __syncthreads();

        // d[c]
        #pragma unroll 4
        for (int j = 0; j < 32; j++) {
            int c = w * 32 + j;
            const float* wr = Wexp + (size_t)c * EE;
            float acc = 0.f;
            #pragma unroll
            for (int k = 0; k < 4; k++)
                acc = fmaf(wr[lane + 32 * k], sp[lane + 32 * k], acc);
            #pragma unroll
            for (int o = 16; o > 0; o >>= 1)
                acc += __shfl_xor_sync(0xFFFFFFFFu, acc, o);
            if (lane == 0) g_d[b * CC + c] = acc + bexp[c];
        }
    }
    gbar();

    // ---------------- P3: out = x + d[b,c], float4 ----------------
    {
        const int total4 = BB * CC * NV;
        const float4* x4 = (const float4*)x;
        float4* o4 = (float4*)out;
        for (int i = bid * TPB + tid; i < total4; i += GRID * TPB) {
            int row = i / NV;
            float dv = g_d[row];
            float4 xv = x4[i];
            float4 o;
            o.x = xv.x + dv; o.y = xv.y + dv; o.z = xv.z + dv; o.w = xv.w + dv;
            o4[i] = o;
        }
    }
}

extern "C" void kernel_launch(void* const* d_in, const int* in_sizes, int n_in,
                              void* d_out, int out_size) {
    const float* x    = (const float*)d_in[0];
    const float* Wq   = (const float*)d_in[1];
    const float* bq   = (const float*)d_in[2];
    const float* Wk   = (const float*)d_in[3];
    const float* bk   = (const float*)d_in[4];
    const float* Wv   = (const float*)d_in[5];
    const float* bv   = (const float*)d_in[6];
    const float* Wcat = (const float*)d_in[7];
    const float* Wexp = (const float*)d_in[8];
    const float* bexp = (const float*)d_in[9];
    float* out = (float*)d_out;

    fused_all<<<GRID, TPB>>>(x, Wq, bq, Wk, bk, Wcat, Wv, bv, Wexp, bexp, out);
}

// round 11
// speedup vs baseline: 1.0120x; 1.0120x over previous
#include <cuda_runtime.h>

#define BB 8
#define CC 256
#define EE 128
#define NN 3136            // 56*56
#define NH 1568            // NN/2
#define TPB 256
#define CHUNK 64
#define NCHK 49            // NN / CHUNK
#define GRID (BB * NCHK)   // 392
#define XSTRIDE 66         // floats per row in xs (64 + 2 pad, float2-aligned)
#define XS_BYTES (CC * XSTRIDE * 4)   // 67584

__device__ float g_ap[16 * CC];
__device__ float g_c0;
__device__ float g_tp[GRID * CC];
__device__ float g_sbp[GRID];
__device__ float g_d[BB * CC];
__device__ unsigned g_fold_cnt;
__device__ unsigned g_bcnt[BB];
__device__ unsigned g_flag[BB];
__device__ unsigned g_exit;

__global__ void __launch_bounds__(TPB, 3)
fused_all(const float* __restrict__ x,
          const float* __restrict__ Wq, const float* __restrict__ bq,
          const float* __restrict__ Wk, const float* __restrict__ bk,
          const float* __restrict__ Wcat,
          const float* __restrict__ Wv, const float* __restrict__ bv,
          const float* __restrict__ Wexp, const float* __restrict__ bexp,
          float* __restrict__ out) {
    extern __shared__ float xs[];      // CC x XSTRIDE
    __shared__ float sa[CC];           // a[] in P1; st[] in P2
    __shared__ float sp[2 * CC];       // y partials (8 warps x 64 n); sm[] in P2
    __shared__ float ss[CHUNK];
    __shared__ float sd[CC];
    __shared__ float s_sbar;
    __shared__ unsigned s_last;

    int tid = threadIdx.x, bid = blockIdx.x;
    int w = tid >> 5, lane = tid & 31;
    int b = bid / NCHK;
    int nchunk = bid - b * NCHK;

    // ---- fold producers (blocks 0..16) ----
    if (bid < 16) {
        float acc = 0.f;
        int e0 = bid * 8;
        #pragma unroll
        for (int k = 0; k < 8; k++) {
            int e = e0 + k;
            acc = fmaf(Wcat[e], Wq[e * CC + tid],
                  fmaf(Wcat[EE + e], Wk[e * CC + tid], acc));
        }
        g_ap[bid * CC + tid] = acc;
        __threadfence();
        __syncthreads();
        if (tid == 0) atomicAdd(&g_fold_cnt, 1u);
    } else if (bid == 16) {
        if (tid < 32) {
            float c0 = 0.f;
            #pragma unroll
            for (int e = tid; e < EE; e += 32)
                c0 = fmaf(Wcat[e], bq[e], fmaf(Wcat[EE + e], bk[e], c0));
            #pragma unroll
            for (int o = 16; o > 0; o >>= 1)
                c0 += __shfl_xor_sync(0xFFFFFFFFu, c0, o);
            if (tid == 0) g_c0 = c0;
        }
        __threadfence();
        __syncthreads();
        if (tid == 0) atomicAdd(&g_fold_cnt, 1u);
    }

    // ---- stage x slice into smem (overlaps fold wait) ----
    float2* xs2 = (float2*)xs;
    const float2* x2 = (const float2*)x;
    float2* o2 = (float2*)out;
    size_t base2 = (size_t)b * CC * NH + nchunk * 32 + lane;
    #pragma unroll
    for (int j = 0; j < 32; j++) {
        int row = w * 32 + j;
        xs2[row * (XSTRIDE / 2) + lane] = x2[base2 + (size_t)row * NH];
    }

    // ---- wait for fold ----
    if (tid == 0) {
        volatile unsigned* fc = &g_fold_cnt;
        while (*fc < 17u) __nanosleep(64);
    }
    __syncthreads();
    __threadfence();
    {
        float a = 0.f;
        #pragma unroll
        for (int k = 0; k < 16; k++) a += g_ap[k * CC + tid];
        sa[tid] = a;
    }
    float c0v = g_c0;
    __syncthreads();

    // ---- y-phase (from smem): warp w covers its 32 c-rows, lane owns n pair ----
    {
        float yx = 0.f, yy = 0.f;
        #pragma unroll
        for (int j = 0; j < 32; j++) {
            int row = w * 32 + j;
            float2 v = xs2[row * (XSTRIDE / 2) + lane];
            float av = sa[row];
            yx = fmaf(av, v.x, yx);
            yy = fmaf(av, v.y, yy);
        }
        ((float2*)sp)[w * 32 + lane] = make_float2(yx, yy);
    }
    __syncthreads();
    if (tid < CHUNK) {
        float v = c0v;
        #pragma unroll
        for (int g = 0; g < 8; g++) v += sp[g * CHUNK + tid];
        ss[tid] = fmaxf(v, 0.f);
    }
    __syncthreads();
    if (tid < 32) {
        float sb = ss[tid] + ss[tid + 32];
        #pragma unroll
        for (int o = 16; o > 0; o >>= 1)
            sb += __shfl_xor_sync(0xFFFFFFFFu, sb, o);
        if (tid == 0) g_sbp[bid] = sb;
    }

    // ---- t-phase: thread owns c = tid; 64 LDS+FMA, no shuffles ----
    {
        const float* xr = xs + tid * XSTRIDE;
        float tacc = 0.f;
        #pragma unroll
        for (int n = 0; n < CHUNK; n++)
            tacc = fmaf(xr[n], ss[n], tacc);
        g_tp[bid * CC + tid] = tacc;
    }
    __threadfence();
    __syncthreads();
    if (tid == 0) s_last = (atomicAdd(&g_bcnt[b], 1u) == NCHK - 1u) ? 1u : 0u;
    __syncthreads();

    // ---- P2 inline on the last-finishing block of b ----
    if (s_last) {
        __threadfence();
        float tv = 0.f;
        #pragma unroll
        for (int k = 0; k < NCHK; k++)
            tv += g_tp[(b * NCHK + k) * CC + tid];
        sa[tid] = tv * (1.0f / NN);
        if (tid < 32) {
            float sb = 0.f;
            for (int k = tid; k < NCHK; k += 32) sb += g_sbp[b * NCHK + k];
            #pragma unroll
            for (int o = 16; o > 0; o >>= 1)
                sb += __shfl_xor_sync(0xFFFFFFFFu, sb, o);
            if (tid == 0) s_sbar = sb * (1.0f / NN);
        }
        __syncthreads();
        float sbar = s_sbar;

        // m[e] -> sp[e]
        #pragma unroll 4
        for (int j = 0; j < 16; j++) {
            int e = w * 16 + j;
            const float* wr = Wv + (size_t)e * CC;
            float acc = 0.f;
            #pragma unroll
            for (int k = 0; k < 8; k++)
                acc = fmaf(wr[lane + 32 * k], sa[lane + 32 * k], acc);
            #pragma unroll
            for (int o = 16; o > 0; o >>= 1)
                acc += __shfl_xor_sync(0xFFFFFFFFu, acc, o);
            if (lane == 0) sp[e] = acc + bv[e] * sbar;
        }
        __syncthreads();

        // d[c]
        #pragma unroll 4
        for (int j = 0; j < 32; j++) {
            int c = w * 32 + j;
            const float* wr = Wexp + (size_t)c * EE;
            float acc = 0.f;
            #pragma unroll
            for (int k = 0; k < 4; k++)
                acc = fmaf(wr[lane + 32 * k], sp[lane + 32 * k], acc);
            #pragma unroll
            for (int o = 16; o > 0; o >>= 1)
                acc += __shfl_xor_sync(0xFFFFFFFFu, acc, o);
            if (lane == 0) g_d[b * CC + c] = acc + bexp[c];
        }
        __threadfence();
        __syncthreads();
        if (tid == 0) atomicExch(&g_flag[b], 1u);
    }

    // ---- P3: wait for d[b], then out slice = xs + d (no global x read) ----
    if (tid == 0) {
        volatile unsigned* fl = &g_flag[b];
        while (*fl == 0u) __nanosleep(64);
    }
    __syncthreads();
    __threadfence();
    sd[tid] = g_d[b * CC + tid];
    __syncthreads();
    #pragma unroll
    for (int j = 0; j < 32; j++) {
        int row = w * 32 + j;
        float2 v = xs2[row * (XSTRIDE / 2) + lane];
        float dv = sd[row];
        v.x += dv; v.y += dv;
        o2[base2 + (size_t)row * NH] = v;
    }

    // ---- exit: last block resets sync state for next graph replay ----
    __syncthreads();
    if (tid == 0) {
        if (atomicAdd(&g_exit, 1u) == GRID - 1u) {
            g_fold_cnt = 0u;
            #pragma unroll
            for (int i = 0; i < BB; i++) { g_bcnt[i] = 0u; g_flag[i] = 0u; }
            __threadfence();
            g_exit = 0u;
        }
    }
}

extern "C" void kernel_launch(void* const* d_in, const int* in_sizes, int n_in,
                              void* d_out, int out_size) {
    const float* x    = (const float*)d_in[0];
    const float* Wq   = (const float*)d_in[1];
    const float* bq   = (const float*)d_in[2];
    const float* Wk   = (const float*)d_in[3];
    const float* bk   = (const float*)d_in[4];
    const float* Wv   = (const float*)d_in[5];
    const float* bv   = (const float*)d_in[6];
    const float* Wcat = (const float*)d_in[7];
    const float* Wexp = (const float*)d_in[8];
    const float* bexp = (const float*)d_in[9];
    float* out = (float*)d_out;

    static int configured = 0;
    if (!configured) {
        cudaFuncSetAttribute(fused_all, cudaFuncAttributeMaxDynamicSharedMemorySize, XS_BYTES);
        configured = 1;
    }
    fused_all<<<GRID, TPB, XS_BYTES>>>(x, Wq, bq, Wk, bk, Wcat, Wv, bv, Wexp, bexp, out);
}

// round 12
// speedup vs baseline: 1.0877x; 1.0749x over previous
#include <cuda_runtime.h>

#define BB 8
#define CC 256
#define EE 128
#define NN 3136            // 56*56
#define NF4 784            // NN/4
#define TPB 256
#define CHUNK 64
#define NCHK 49            // NN / CHUNK
#define GRID (BB * NCHK)   // 392
#define XSTRIDE 68         // floats per xs row (64 + 4 pad; 272B, float4-aligned)
#define XS_BYTES (CC * XSTRIDE * 4)   // 69632

__device__ float g_ap[16 * CC];
__device__ float g_c0;
__device__ float g_mp[GRID * EE];   // partial m per (b,chunk)
__device__ float g_sbp[GRID];
__device__ float g_d[BB * CC];
__device__ float g_dummy;
__device__ unsigned g_fold_cnt;
__device__ unsigned g_bcnt[BB];
__device__ unsigned g_flag[BB];
__device__ unsigned g_exit;

__global__ void __launch_bounds__(TPB, 3)
fused_all(const float* __restrict__ x,
          const float* __restrict__ Wq, const float* __restrict__ bq,
          const float* __restrict__ Wk, const float* __restrict__ bk,
          const float* __restrict__ Wcat,
          const float* __restrict__ Wv, const float* __restrict__ bv,
          const float* __restrict__ Wexp, const float* __restrict__ bexp,
          float* __restrict__ out) {
    extern __shared__ float xs[];      // CC x XSTRIDE
    __shared__ float sa[CC];           // a[] in P1; m[] in leader
    __shared__ float sp[2 * CC];       // y partials; t[] later
    __shared__ float ss[CHUNK];
    __shared__ float sd[CC];
    __shared__ float s_sbar;
    __shared__ unsigned s_last;

    int tid = threadIdx.x, bid = blockIdx.x;
    int w = tid >> 5, lane = tid & 31;
    int b = bid / NCHK;
    int nchunk = bid - b * NCHK;

    // ---- fold producers (blocks 0..16); L2 prefetch of Wv/Wexp (17..80) ----
    if (bid < 16) {
        float acc = 0.f;
        int e0 = bid * 8;
        #pragma unroll
        for (int k = 0; k < 8; k++) {
            int e = e0 + k;
            acc = fmaf(Wcat[e], Wq[e * CC + tid],
                  fmaf(Wcat[EE + e], Wk[e * CC + tid], acc));
        }
        g_ap[bid * CC + tid] = acc;
        __threadfence();
        __syncthreads();
        if (tid == 0) atomicAdd(&g_fold_cnt, 1u);
    } else if (bid == 16) {
        if (tid < 32) {
            float c0 = 0.f;
            #pragma unroll
            for (int e = tid; e < EE; e += 32)
                c0 = fmaf(Wcat[e], bq[e], fmaf(Wcat[EE + e], bk[e], c0));
            #pragma unroll
            for (int o = 16; o > 0; o >>= 1)
                c0 += __shfl_xor_sync(0xFFFFFFFFu, c0, o);
            if (tid == 0) g_c0 = c0;
        }
        __threadfence();
        __syncthreads();
        if (tid == 0) atomicAdd(&g_fold_cnt, 1u);
    } else if (bid < 81) {
        int i = bid - 17;
        const float4* src = (i < 32) ? (const float4*)(Wv + i * 1024)
                                     : (const float4*)(Wexp + (i - 32) * 1024);
        float4 v = src[tid];
        float sum = v.x + v.y + v.z + v.w;
        if (sum == -1.2345e38f) g_dummy = sum;   // keep prefetch alive
    }

    // ---- stage x slice (float4, two batches), overlaps fold wait ----
    const float4* x4 = (const float4*)x;
    float4* o4 = (float4*)out;
    int colv = tid & 15, row0 = tid >> 4;
    size_t gbase = (size_t)b * CC * NF4 + nchunk * 16 + colv;
    #pragma unroll
    for (int k = 0; k < 8; k++) {
        int row = row0 + 16 * k;
        *(float4*)(xs + row * XSTRIDE + colv * 4) = x4[gbase + (size_t)row * NF4];
    }
    __syncthreads();
    #pragma unroll
    for (int k = 8; k < 16; k++) {
        int row = row0 + 16 * k;
        *(float4*)(xs + row * XSTRIDE + colv * 4) = x4[gbase + (size_t)row * NF4];
    }

    // ---- wait for fold, build a[] ----
    if (tid == 0) {
        volatile unsigned* fc = &g_fold_cnt;
        while (*fc < 17u) __nanosleep(64);
    }
    __syncthreads();
    __threadfence();
    {
        float a = 0.f;
        #pragma unroll
        for (int k = 0; k < 16; k++) a += g_ap[k * CC + tid];
        sa[tid] = a;
    }
    float c0v = g_c0;
    __syncthreads();

    // ---- y-phase: warp w covers rows w*32..+31, lane owns an n-pair ----
    {
        float yx = 0.f, yy = 0.f;
        #pragma unroll
        for (int j = 0; j < 32; j++) {
            int row = w * 32 + j;
            float2 v = *(float2*)(xs + row * XSTRIDE + lane * 2);
            float av = sa[row];
            yx = fmaf(av, v.x, yx);
            yy = fmaf(av, v.y, yy);
        }
        ((float2*)sp)[w * 32 + lane] = make_float2(yx, yy);
    }
    __syncthreads();
    if (tid < 32) {
        float ax = c0v, ay = c0v;
        #pragma unroll
        for (int g = 0; g < 8; g++) {
            float2 q = ((float2*)sp)[g * 32 + tid];
            ax += q.x; ay += q.y;
        }
        ax = fmaxf(ax, 0.f); ay = fmaxf(ay, 0.f);
        ss[2 * tid] = ax; ss[2 * tid + 1] = ay;
        float sb = ax + ay;
        #pragma unroll
        for (int o = 16; o > 0; o >>= 1)
            sb += __shfl_xor_sync(0xFFFFFFFFu, sb, o);
        if (tid == 0) g_sbp[bid] = sb;
    }
    __syncthreads();

    // ---- t-phase: thread owns c = tid, skewed start (conflict-free) ----
    {
        const float* xr = xs + tid * XSTRIDE;
        float tacc = 0.f;
        #pragma unroll
        for (int i = 0; i < CHUNK; i++) {
            int n = (tid + i) & 63;
            tacc = fmaf(xr[n], ss[n], tacc);
        }
        sp[tid] = tacc;      // sp now holds t partials (raw)
    }
    __syncthreads();

    // ---- partial m: warp w computes e = w*16..+15 (Wv L2-hot) ----
    {
        float mv = 0.f;
        #pragma unroll 4
        for (int j = 0; j < 16; j++) {
            int e = w * 16 + j;
            const float* wr = Wv + (size_t)e * CC;
            float acc = 0.f;
            #pragma unroll
            for (int k = 0; k < 8; k++)
                acc = fmaf(wr[lane + 32 * k], sp[lane + 32 * k], acc);
            #pragma unroll
            for (int o = 16; o > 0; o >>= 1)
                acc += __shfl_xor_sync(0xFFFFFFFFu, acc, o);
            if (lane == j) mv = acc;
        }
        if (lane < 16) g_mp[bid * EE + w * 16 + lane] = mv;
    }
    __threadfence();
    __syncthreads();
    if (tid == 0) s_last = (atomicAdd(&g_bcnt[b], 1u) == NCHK - 1u) ? 1u : 0u;
    __syncthreads();

    // ---- leader: sum mp + sbar, then d matvec (Wexp L2-hot) ----
    if (s_last) {
        __threadfence();
        if (tid < 32) {
            float sb = 0.f;
            for (int k = tid; k < NCHK; k += 32) sb += g_sbp[b * NCHK + k];
            #pragma unroll
            for (int o = 16; o > 0; o >>= 1)
                sb += __shfl_xor_sync(0xFFFFFFFFu, sb, o);
            if (tid == 0) s_sbar = sb * (1.0f / NN);
        }
        __syncthreads();
        float sbar = s_sbar;
        if (tid < EE) {
            float mm = 0.f;
            #pragma unroll
            for (int k = 0; k < NCHK; k++)
                mm += g_mp[(b * NCHK + k) * EE + tid];
            sa[tid] = mm * (1.0f / NN) + bv[tid] * sbar;
        }
        __syncthreads();
        {
            float dd = 0.f;
            #pragma unroll 4
            for (int j = 0; j < 32; j++) {
                int c = w * 32 + j;
                const float* wr = Wexp + (size_t)c * EE;
                float acc = 0.f;
                #pragma unroll
                for (int k = 0; k < 4; k++)
                    acc = fmaf(wr[lane + 32 * k], sa[lane + 32 * k], acc);
                #pragma unroll
                for (int o = 16; o > 0; o >>= 1)
                    acc += __shfl_xor_sync(0xFFFFFFFFu, acc, o);
                if (lane == j) dd = acc;
            }
            g_d[b * CC + w * 32 + lane] = dd + bexp[w * 32 + lane];
        }
        __threadfence();
        __syncthreads();
        if (tid == 0) atomicExch(&g_flag[b], 1u);
    }

    // ---- P3: wait for d[b], write out = xs + d (no global x read) ----
    if (tid == 0) {
        volatile unsigned* fl = &g_flag[b];
        while (*fl == 0u) __nanosleep(64);
    }
    __syncthreads();
    __threadfence();
    sd[tid] = g_d[b * CC + tid];
    __syncthreads();
    #pragma unroll
    for (int k = 0; k < 16; k++) {
        int row = row0 + 16 * k;
        float4 v = *(float4*)(xs + row * XSTRIDE + colv * 4);
        float dv = sd[row];
        v.x += dv; v.y += dv; v.z += dv; v.w += dv;
        o4[gbase + (size_t)row * NF4] = v;
    }

    // ---- exit: last block resets sync state for next graph replay ----
    __syncthreads();
    if (tid == 0) {
        if (atomicAdd(&g_exit, 1u) == GRID - 1u) {
            g_fold_cnt = 0u;
            #pragma unroll
            for (int i = 0; i < BB; i++) { g_bcnt[i] = 0u; g_flag[i] = 0u; }
            __threadfence();
            g_exit = 0u;
        }
    }
}

extern "C" void kernel_launch(void* const* d_in, const int* in_sizes, int n_in,
                              void* d_out, int out_size) {
    const float* x    = (const float*)d_in[0];
    const float* Wq   = (const float*)d_in[1];
    const float* bq   = (const float*)d_in[2];
    const float* Wk   = (const float*)d_in[3];
    const float* bk   = (const float*)d_in[4];
    const float* Wv   = (const float*)d_in[5];
    const float* bv   = (const float*)d_in[6];
    const float* Wcat = (const float*)d_in[7];
    const float* Wexp = (const float*)d_in[8];
    const float* bexp = (const float*)d_in[9];
    float* out = (float*)d_out;

    static int configured = 0;
    if (!configured) {
        cudaFuncSetAttribute(fused_all, cudaFuncAttributeMaxDynamicSharedMemorySize, XS_BYTES);
        configured = 1;
    }
    fused_all<<<GRID, TPB, XS_BYTES>>>(x, Wq, bq, Wk, bk, Wcat, Wv, bv, Wexp, bexp, out);
}